// round 12
// baseline (speedup 1.0000x reference)
#include <cuda_runtime.h>
#include <cuda_bf16.h>

// Table-batched EmbeddingBag forward (SUM pooling).
// T=8 tables, B=8192 batch, D=128 dim, ROWS=200000 rows/table.
// Persistent single-wave grid; one warp per bag per pass; lane l owns
// one float4 of the D=128 row (512B coalesced gather per row).
// Indices loaded as int4 (one broadcast LDG.128 per 4 rows, no prefetch
// pipeline -> no register cost). Streaming cache hints: __ldcs on the
// single-use index stream, __stcs on the never-re-read output, keeping
// L2 capacity for weight-row duplicate hits.

#ifndef EMB_T
#define EMB_T 8
#define EMB_B 8192
#define EMB_D 128
#define EMB_ROWS 200000
#endif

#define D4 (EMB_D / 4)          // float4 per row = 32
#define NUM_SMS 148
#define BLOCKS_PER_SM 8

__device__ __forceinline__ void facc(float4& a, const float4& v) {
    a.x += v.x; a.y += v.y; a.z += v.z; a.w += v.w;
}

__global__ __launch_bounds__(256, 8) void emb_bag_sum_kernel(
    const int* __restrict__ indices,
    const int* __restrict__ offsets,
    const float4* __restrict__ weights4,
    float4* __restrict__ out4,
    int n_bags)
{
    const int lane        = threadIdx.x & 31;
    const int warp_global = (blockIdx.x * blockDim.x + threadIdx.x) >> 5;
    const int warp_stride = (gridDim.x * blockDim.x) >> 5;

    for (int bag = warp_global; bag < n_bags; bag += warp_stride) {
        const int feature = bag / EMB_B;
        const int b       = bag - feature * EMB_B;

        const int start = __ldg(offsets + bag);
        const int end   = __ldg(offsets + bag + 1);
        const int n     = end - start;

        const float4* __restrict__ tbl =
            weights4 + (size_t)feature * EMB_ROWS * D4 + lane;

        float4 a0 = make_float4(0.f, 0.f, 0.f, 0.f);
        float4 a1 = make_float4(0.f, 0.f, 0.f, 0.f);

        const int* ibase = indices + start;
        if ((((unsigned long long)ibase & 15ull) == 0ull) && ((n & 3) == 0)) {
            // Fast path (L=20 uniform offsets -> always taken).
            const int4* __restrict__ idx4 = (const int4*)ibase;
            const int nchunks = n >> 2;
            for (int c = 0; c < nchunks; ++c) {
                const int4 r = __ldcs(idx4 + c);   // single-use: stream it
                const float4 v0 = __ldg(tbl + (size_t)r.x * D4);
                const float4 v1 = __ldg(tbl + (size_t)r.y * D4);
                const float4 v2 = __ldg(tbl + (size_t)r.z * D4);
                const float4 v3 = __ldg(tbl + (size_t)r.w * D4);
                facc(a0, v0); facc(a1, v1); facc(a0, v2); facc(a1, v3);
            }
        } else {
            // Generic ragged fallback.
            #pragma unroll 4
            for (int j = start; j < end; ++j) {
                const int r = __ldg(indices + j);
                facc(a0, __ldg(tbl + (size_t)r * D4));
            }
        }

        facc(a0, a1);

        const size_t o = (size_t)b * (EMB_T * D4)
                       + (size_t)feature * D4 + lane;
        __stcs(out4 + o, a0);   // never re-read: bypass/evict-first in L2
    }
}

extern "C" void kernel_launch(void* const* d_in, const int* in_sizes, int n_in,
                              void* d_out, int out_size)
{
    const int*   indices = (const int*)d_in[0];
    const int*   offsets = (const int*)d_in[1];
    const float* weights = (const float*)d_in[2];

    const int n_bags = in_sizes[1] - 1;      // T*B
    int blocks = NUM_SMS * BLOCKS_PER_SM;    // one resident wave
    const int max_blocks = (n_bags + 7) / 8; // never launch idle blocks
    if (blocks > max_blocks) blocks = max_blocks;

    emb_bag_sum_kernel<<<blocks, 256>>>(
        indices, offsets,
        (const float4*)weights, (float4*)d_out, n_bags);
}

// round 13
// speedup vs baseline: 1.1471x; 1.1471x over previous
#include <cuda_runtime.h>
#include <cuda_bf16.h>

// Table-batched EmbeddingBag forward (SUM pooling).
// T=8 tables, B=8192 batch, D=128 dim, ROWS=200000 rows/table.
// indices: [nnz] int32, offsets: [T*B+1] int32, weights: flat
// [T*ROWS*D] float32. out: [B, T*D] float32.
//
// One warp per bag. Lane l owns floats [4l, 4l+4) of the D=128 row
// (one float4); each row gather is a fully-coalesced 512B read.
// Empirical optimum across 6 measured variants: simple dependent loop,
// scalar broadcast index loads (4 independent in flight via unroll),
// no cache hints, no pipelining, 32 regs / ~89% occupancy. DRAM
// saturates at ~75% (6.2 TB/s) = random-512B-row HBM ceiling at the
// distinct-row traffic floor; all restructuring attempts regressed.

#ifndef EMB_T
#define EMB_T 8
#define EMB_B 8192
#define EMB_D 128
#define EMB_ROWS 200000
#endif

__global__ __launch_bounds__(256) void emb_bag_sum_kernel(
    const int* __restrict__ indices,
    const int* __restrict__ offsets,
    const float4* __restrict__ weights4,   // weights viewed as float4 (32 per row)
    float4* __restrict__ out4,             // out viewed as float4
    int n_bags)
{
    const int warp_id = (blockIdx.x * blockDim.x + threadIdx.x) >> 5;
    const int lane    = threadIdx.x & 31;
    if (warp_id >= n_bags) return;

    const int bag = warp_id;
    const int feature = bag / EMB_B;        // table id
    const int b       = bag - feature * EMB_B;

    const int start = __ldg(offsets + bag);
    const int end   = __ldg(offsets + bag + 1);

    // float4 row stride = D/4 = 32; table base in float4 units
    const long long feat_base = (long long)feature * EMB_ROWS;

    float4 acc = make_float4(0.f, 0.f, 0.f, 0.f);

    #pragma unroll 4
    for (int j = start; j < end; ++j) {
        const int row = __ldg(indices + j);
        const long long grow = feat_base + row;
        float4 v = __ldg(weights4 + grow * (EMB_D / 4) + lane);
        acc.x += v.x; acc.y += v.y; acc.z += v.z; acc.w += v.w;
    }

    // out[b, feature*D + lane*4 .. +4)  -> float4 index
    const long long o = (long long)b * (EMB_T * EMB_D / 4)
                      + feature * (EMB_D / 4) + lane;
    out4[o] = acc;
}

extern "C" void kernel_launch(void* const* d_in, const int* in_sizes, int n_in,
                              void* d_out, int out_size)
{
    const int*   indices = (const int*)d_in[0];
    const int*   offsets = (const int*)d_in[1];
    const float* weights = (const float*)d_in[2];

    const int n_bags = in_sizes[1] - 1;         // T*B
    const int warps_per_block = 256 / 32;       // 8
    const int blocks = (n_bags + warps_per_block - 1) / warps_per_block;

    emb_bag_sum_kernel<<<blocks, 256>>>(
        indices, offsets,
        (const float4*)weights, (float4*)d_out, n_bags);
}

// round 14
// speedup vs baseline: 1.2000x; 1.0461x over previous
#include <cuda_runtime.h>
#include <cuda_bf16.h>

// Table-batched EmbeddingBag forward (SUM pooling).
// T=8 tables, B=8192 batch, D=128 dim, ROWS=200000 rows/table.
// indices: [nnz] int32, offsets: [T*B+1] int32, weights: flat
// [T*ROWS*D] float32. out: [B, T*D] float32.
//
// One warp per bag. Lane l owns floats [4l, 4l+4) of the D=128 row
// (one float4); each row gather is a fully-coalesced 512B read.
// Empirical optimum across 7 measured variants: simple dependent loop,
// scalar broadcast index loads (4 independent in flight via unroll),
// no cache hints, no pipelining, 32 regs / ~88% occupancy. DRAM
// saturates at ~75% (6.1-6.2 TB/s) = random-512B-row HBM ceiling at
// the distinct-row traffic floor; all restructuring regressed.
// This revision only hoists the per-warp table base pointer and uses
// 32-bit within-table offsets (table = 102MB < 4GB), shortening the
// index->address->LDG dependent chain.

#ifndef EMB_T
#define EMB_T 8
#define EMB_B 8192
#define EMB_D 128
#define EMB_ROWS 200000
#endif

#define D4 (EMB_D / 4)   // float4 per row = 32

__global__ __launch_bounds__(256) void emb_bag_sum_kernel(
    const int* __restrict__ indices,
    const int* __restrict__ offsets,
    const float4* __restrict__ weights4,   // weights viewed as float4
    float4* __restrict__ out4,             // out viewed as float4
    int n_bags)
{
    const int warp_id = (blockIdx.x * blockDim.x + threadIdx.x) >> 5;
    const int lane    = threadIdx.x & 31;
    if (warp_id >= n_bags) return;

    const int bag     = warp_id;
    const int feature = bag / EMB_B;        // table id
    const int b       = bag - feature * EMB_B;

    const int start = __ldg(offsets + bag);
    const int end   = __ldg(offsets + bag + 1);

    // Per-warp base: table start + this lane's float4 within the row.
    // Within-table offsets (row * 32 float4s, max 6.4M) fit in 32 bits.
    const float4* __restrict__ tbl =
        weights4 + (size_t)feature * EMB_ROWS * D4 + lane;

    float4 acc = make_float4(0.f, 0.f, 0.f, 0.f);

    #pragma unroll 4
    for (int j = start; j < end; ++j) {
        const unsigned row = (unsigned)__ldg(indices + j);
        const float4 v = __ldg(tbl + row * (unsigned)D4);
        acc.x += v.x; acc.y += v.y; acc.z += v.z; acc.w += v.w;
    }

    const size_t o = (size_t)b * (EMB_T * D4) + (size_t)feature * D4 + lane;
    out4[o] = acc;
}

extern "C" void kernel_launch(void* const* d_in, const int* in_sizes, int n_in,
                              void* d_out, int out_size)
{
    const int*   indices = (const int*)d_in[0];
    const int*   offsets = (const int*)d_in[1];
    const float* weights = (const float*)d_in[2];

    const int n_bags = in_sizes[1] - 1;         // T*B
    const int warps_per_block = 256 / 32;       // 8
    const int blocks = (n_bags + warps_per_block - 1) / warps_per_block;

    emb_bag_sum_kernel<<<blocks, 256>>>(
        indices, offsets,
        (const float4*)weights, (float4*)d_out, n_bags);
}